// round 4
// baseline (speedup 1.0000x reference)
#include <cuda_runtime.h>
#include <cstdint>

// Problem constants
#define T_TOK 2048
#define H_DIM 4096
#define O_DIM 4096
#define L_NUM 32
#define R_RANK 16

// Scratch (no cudaMalloc allowed)
__device__ int   g_idx[T_TOK];
__device__ float g_shrunk[T_TOK * R_RANK];

// ---------------------------------------------------------------------------
// Kernel 0: normalize indices. The reference creates int64 indices, but JAX
// silently downcasts to int32 when x64 is disabled. Detect which one we got:
// for little-endian int64 values in [-1, 31], every odd int32 word is the
// sign-extension (0 or -1) of the even word. Check 1024 pairs; random int32
// index data cannot satisfy all of them.
// ---------------------------------------------------------------------------
__global__ void prep_indices_kernel(const void* __restrict__ idx_raw) {
    __shared__ int all64;
    int tid = threadIdx.x;  // 1024 threads
    if (tid == 0) all64 = 1;
    __syncthreads();

    const int* p32 = (const int*)idx_raw;
    int lo = p32[2 * tid];
    int hi = p32[2 * tid + 1];
    bool ok = (hi == ((lo < 0) ? -1 : 0)) && (lo >= -1) && (lo < 64);
    if (!ok) atomicAnd(&all64, 0);
    __syncthreads();

    if (all64) {
        const long long* p64 = (const long long*)idx_raw;
        g_idx[tid]        = (int)p64[tid];
        g_idx[tid + 1024] = (int)p64[tid + 1024];
    } else {
        g_idx[tid]        = p32[tid];
        g_idx[tid + 1024] = p32[tid + 1024];
    }
}

// ---------------------------------------------------------------------------
// Kernel 1: LoRA shrink. shrunk[t][r] = sum_h x[t][h] * A[idx[t]][r][h]
// One block per token; x row staged in SMEM; 8 warps, each warp does 2 ranks
// with full-width float4 reduction + shuffle.
// ---------------------------------------------------------------------------
__global__ __launch_bounds__(256) void lora_shrink_kernel(
    const float* __restrict__ x, const float* __restrict__ lora_a) {
    int t = blockIdx.x;
    int id = g_idx[t];
    int tid = threadIdx.x;

    if (id < 0) {
        if (tid < R_RANK) g_shrunk[t * R_RANK + tid] = 0.0f;
        return;
    }

    __shared__ float xs[H_DIM];
    const float4* xrow = (const float4*)(x + (size_t)t * H_DIM);
    for (int i = tid; i < H_DIM / 4; i += 256)
        ((float4*)xs)[i] = xrow[i];
    __syncthreads();

    int w = tid >> 5, lane = tid & 31;
    const float* Abase = lora_a + ((size_t)id * R_RANK) * H_DIM;

    for (int r = w; r < R_RANK; r += 8) {
        const float4* arow = (const float4*)(Abase + (size_t)r * H_DIM);
        float s = 0.0f;
        for (int h4 = lane; h4 < H_DIM / 4; h4 += 32) {
            float4 a = arow[h4];
            float4 xv = ((const float4*)xs)[h4];
            s += a.x * xv.x + a.y * xv.y + a.z * xv.z + a.w * xv.w;
        }
        #pragma unroll
        for (int o = 16; o > 0; o >>= 1) s += __shfl_xor_sync(0xffffffffu, s, o);
        if (lane == 0) g_shrunk[t * R_RANK + r] = s;
    }
}

// ---------------------------------------------------------------------------
// Kernel 2: base GEMM. C[t][o] = sum_h x[t][h]*W[o][h] + bias[o]
// 128x128 tile, BK=8, 8x8 microtile per thread, 256 threads, float4 I/O.
// ---------------------------------------------------------------------------
#define BM 128
#define BN 128
#define BK 8
__global__ __launch_bounds__(256, 2) void sgemm_bias_kernel(
    const float* __restrict__ A,   // x: (T, H)
    const float* __restrict__ W,   // weight: (O, H)
    const float* __restrict__ bias,
    float* __restrict__ C) {       // out: (T, O)
    const int K = H_DIM, N = O_DIM;
    __shared__ float As[BK][BM];
    __shared__ float Bs[BK][BN];

    int tid = threadIdx.x;
    int brow = blockIdx.y;  // M tile
    int bcol = blockIdx.x;  // N tile
    int ty = tid >> 4;      // 0..15
    int tx = tid & 15;      // 0..15

    int ldRow = tid >> 1;
    int ldK   = (tid & 1) * 4;
    const float* Aptr = A + ((size_t)brow * BM + ldRow) * K + ldK;
    const float* Wptr = W + ((size_t)bcol * BN + ldRow) * K + ldK;

    float acc[8][8];
    #pragma unroll
    for (int i = 0; i < 8; i++)
        #pragma unroll
        for (int j = 0; j < 8; j++) acc[i][j] = 0.0f;

    for (int k0 = 0; k0 < K; k0 += BK) {
        float4 av = *(const float4*)(Aptr + k0);
        float4 bv = *(const float4*)(Wptr + k0);
        As[ldK + 0][ldRow] = av.x;
        As[ldK + 1][ldRow] = av.y;
        As[ldK + 2][ldRow] = av.z;
        As[ldK + 3][ldRow] = av.w;
        Bs[ldK + 0][ldRow] = bv.x;
        Bs[ldK + 1][ldRow] = bv.y;
        Bs[ldK + 2][ldRow] = bv.z;
        Bs[ldK + 3][ldRow] = bv.w;
        __syncthreads();

        #pragma unroll
        for (int k = 0; k < BK; k++) {
            float4 a0 = *(const float4*)&As[k][ty * 8];
            float4 a1 = *(const float4*)&As[k][ty * 8 + 4];
            float4 b0 = *(const float4*)&Bs[k][tx * 8];
            float4 b1 = *(const float4*)&Bs[k][tx * 8 + 4];
            float ra[8] = {a0.x, a0.y, a0.z, a0.w, a1.x, a1.y, a1.z, a1.w};
            float rb[8] = {b0.x, b0.y, b0.z, b0.w, b1.x, b1.y, b1.z, b1.w};
            #pragma unroll
            for (int i = 0; i < 8; i++)
                #pragma unroll
                for (int j = 0; j < 8; j++)
                    acc[i][j] += ra[i] * rb[j];
        }
        __syncthreads();
    }

    int row0 = brow * BM + ty * 8;
    int col0 = bcol * BN + tx * 8;
    float4 bb0 = *(const float4*)&bias[col0];
    float4 bb1 = *(const float4*)&bias[col0 + 4];
    #pragma unroll
    for (int i = 0; i < 8; i++) {
        float4 v0 = make_float4(acc[i][0] + bb0.x, acc[i][1] + bb0.y,
                                acc[i][2] + bb0.z, acc[i][3] + bb0.w);
        float4 v1 = make_float4(acc[i][4] + bb1.x, acc[i][5] + bb1.y,
                                acc[i][6] + bb1.z, acc[i][7] + bb1.w);
        float* crow = C + (size_t)(row0 + i) * N + col0;
        *(float4*)(crow)     = v0;
        *(float4*)(crow + 4) = v1;
    }
}

// ---------------------------------------------------------------------------
// Kernel 3: LoRA expand. out[t][o] += sum_r shrunk[t][r] * B[idx[t]][o][r]
// lora_b rows (R=16 floats = 64B) are contiguous -> 4x float4 per (t,o).
// ---------------------------------------------------------------------------
__global__ __launch_bounds__(256) void lora_expand_kernel(
    const float* __restrict__ lora_b, float* __restrict__ out) {
    int t = blockIdx.y;
    int id = g_idx[t];
    if (id < 0) return;

    __shared__ float s[R_RANK];
    if (threadIdx.x < R_RANK) s[threadIdx.x] = g_shrunk[t * R_RANK + threadIdx.x];
    __syncthreads();

    int o = blockIdx.x * 256 + threadIdx.x;
    const float4* B = (const float4*)(lora_b + (((size_t)id * O_DIM) + o) * R_RANK);
    float4 b0 = B[0], b1 = B[1], b2 = B[2], b3 = B[3];
    float acc = s[0] * b0.x + s[1] * b0.y + s[2] * b0.z + s[3] * b0.w
              + s[4] * b1.x + s[5] * b1.y + s[6] * b1.z + s[7] * b1.w
              + s[8] * b2.x + s[9] * b2.y + s[10] * b2.z + s[11] * b2.w
              + s[12] * b3.x + s[13] * b3.y + s[14] * b3.z + s[15] * b3.w;
    out[(size_t)t * O_DIM + o] += acc;
}

// ---------------------------------------------------------------------------
extern "C" void kernel_launch(void* const* d_in, const int* in_sizes, int n_in,
                              void* d_out, int out_size) {
    const float* x      = (const float*)d_in[0];
    const float* weight = (const float*)d_in[1];
    const float* bias   = (const float*)d_in[2];
    const float* lora_a = (const float*)d_in[3];
    const float* lora_b = (const float*)d_in[4];
    const void*  idxraw = d_in[5];
    float* out = (float*)d_out;

    prep_indices_kernel<<<1, 1024>>>(idxraw);
    lora_shrink_kernel<<<T_TOK, 256>>>(x, lora_a);
    dim3 ggrid(O_DIM / BN, T_TOK / BM);
    sgemm_bias_kernel<<<ggrid, 256>>>(x, weight, bias, out);
    dim3 egrid(O_DIM / 256, T_TOK);
    lora_expand_kernel<<<egrid, 256>>>(lora_b, out);
}

// round 5
// speedup vs baseline: 2.7646x; 2.7646x over previous
#include <cuda_runtime.h>
#include <cstdint>

// Problem constants
#define T_TOK 2048
#define H_DIM 4096
#define O_DIM 4096
#define L_NUM 32
#define R_RANK 16

// Scratch (no cudaMalloc allowed)
__device__ int   g_idx[T_TOK];
__device__ float g_shrunk[T_TOK * R_RANK];

// ---------------------------------------------------------------------------
// Kernel 0: normalize indices (int64-vs-int32 autodetect, as before).
// ---------------------------------------------------------------------------
__global__ void prep_indices_kernel(const void* __restrict__ idx_raw) {
    __shared__ int all64;
    int tid = threadIdx.x;  // 1024 threads
    if (tid == 0) all64 = 1;
    __syncthreads();

    const int* p32 = (const int*)idx_raw;
    int lo = p32[2 * tid];
    int hi = p32[2 * tid + 1];
    bool ok = (hi == ((lo < 0) ? -1 : 0)) && (lo >= -1) && (lo < 64);
    if (!ok) atomicAnd(&all64, 0);
    __syncthreads();

    if (all64) {
        const long long* p64 = (const long long*)idx_raw;
        g_idx[tid]        = (int)p64[tid];
        g_idx[tid + 1024] = (int)p64[tid + 1024];
    } else {
        g_idx[tid]        = p32[tid];
        g_idx[tid + 1024] = p32[tid + 1024];
    }
}

// ---------------------------------------------------------------------------
// Kernel 1: LoRA shrink (unchanged).
// ---------------------------------------------------------------------------
__global__ __launch_bounds__(256) void lora_shrink_kernel(
    const float* __restrict__ x, const float* __restrict__ lora_a) {
    int t = blockIdx.x;
    int id = g_idx[t];
    int tid = threadIdx.x;

    if (id < 0) {
        if (tid < R_RANK) g_shrunk[t * R_RANK + tid] = 0.0f;
        return;
    }

    __shared__ float xs[H_DIM];
    const float4* xrow = (const float4*)(x + (size_t)t * H_DIM);
    for (int i = tid; i < H_DIM / 4; i += 256)
        ((float4*)xs)[i] = xrow[i];
    __syncthreads();

    int w = tid >> 5, lane = tid & 31;
    const float* Abase = lora_a + ((size_t)id * R_RANK) * H_DIM;

    for (int r = w; r < R_RANK; r += 8) {
        const float4* arow = (const float4*)(Abase + (size_t)r * H_DIM);
        float s = 0.0f;
        for (int h4 = lane; h4 < H_DIM / 4; h4 += 32) {
            float4 a = arow[h4];
            float4 xv = ((const float4*)xs)[h4];
            s += a.x * xv.x + a.y * xv.y + a.z * xv.z + a.w * xv.w;
        }
        #pragma unroll
        for (int o = 16; o > 0; o >>= 1) s += __shfl_xor_sync(0xffffffffu, s, o);
        if (lane == 0) g_shrunk[t * R_RANK + r] = s;
    }
}

// ---------------------------------------------------------------------------
// Kernel 2: base GEMM on TENSOR CORES (tf32 mma.sync, fp32 accumulate).
// CTA tile 128x128x16, 3-stage cp.async pipeline, warp tile 64x32.
// SMEM rows padded 16->20 floats: fragment LDS pattern (8 rows x 4 cols,
// addr = gid*20 + tig) hits 32 distinct banks -> conflict-free.
// ---------------------------------------------------------------------------
#define BM 128
#define BN 128
#define BK 16
#define STAGES 3
#define ROWSTRIDE 20
#define SLICE (128 * ROWSTRIDE)   // floats per tile per stage

__device__ __forceinline__ uint32_t f2tf32(float f) {
    uint32_t r;
    asm("cvt.rna.tf32.f32 %0, %1;\n" : "=r"(r) : "f"(f));
    return r;
}

__device__ __forceinline__ void mma_tf32(float* c, const uint32_t* a, const uint32_t* b) {
    asm volatile(
        "mma.sync.aligned.m16n8k8.row.col.f32.tf32.tf32.f32 "
        "{%0,%1,%2,%3}, {%4,%5,%6,%7}, {%8,%9}, {%0,%1,%2,%3};\n"
        : "+f"(c[0]), "+f"(c[1]), "+f"(c[2]), "+f"(c[3])
        : "r"(a[0]), "r"(a[1]), "r"(a[2]), "r"(a[3]), "r"(b[0]), "r"(b[1]));
}

__global__ __launch_bounds__(256, 2) void tf32_gemm_bias_kernel(
    const float* __restrict__ A,   // x: (T, H)
    const float* __restrict__ W,   // weight: (O, H)
    const float* __restrict__ bias,
    float* __restrict__ C) {       // out: (T, O)
    extern __shared__ float smem[];
    float* Abuf = smem;                   // STAGES * SLICE
    float* Bbuf = smem + STAGES * SLICE;  // STAGES * SLICE

    const int tid  = threadIdx.x;
    const int brow = blockIdx.y;
    const int bcol = blockIdx.x;
    const int warp = tid >> 5, lane = tid & 31;
    const int gid  = lane >> 2, tig = lane & 3;
    const int mw   = warp >> 2;          // 0..1
    const int nw   = warp & 3;           // 0..3
    const int m0   = mw * 64;
    const int n0   = nw * 32;

    const float* Ag = A + (size_t)(brow * BM) * H_DIM;
    const float* Wg = W + (size_t)(bcol * BN) * H_DIM;

    // global->smem: 512 16B chunks per tile, 2 per thread per tile
    const int row0 = tid >> 2,          kc0 = (tid & 3) * 4;
    const int row1 = (tid + 256) >> 2,  kc1 = kc0;  // q=tid+256: row=tid>>2 + 64, kc same

    float acc[4][4][4];
    #pragma unroll
    for (int i = 0; i < 4; i++)
        #pragma unroll
        for (int j = 0; j < 4; j++)
            #pragma unroll
            for (int c = 0; c < 4; c++) acc[i][j][c] = 0.0f;

    const int NK = H_DIM / BK;  // 256

    // ---- pipeline prologue ----
    #pragma unroll
    for (int s = 0; s < STAGES - 1; s++) {
        int kof = s * BK;
        {
            uint32_t sa = (uint32_t)__cvta_generic_to_shared(
                &Abuf[s * SLICE + row0 * ROWSTRIDE + kc0]);
            uint32_t sb = (uint32_t)__cvta_generic_to_shared(
                &Bbuf[s * SLICE + row0 * ROWSTRIDE + kc0]);
            asm volatile("cp.async.cg.shared.global [%0], [%1], 16;\n"
                         :: "r"(sa), "l"(Ag + (size_t)row0 * H_DIM + kof + kc0));
            asm volatile("cp.async.cg.shared.global [%0], [%1], 16;\n"
                         :: "r"(sb), "l"(Wg + (size_t)row0 * H_DIM + kof + kc0));
        }
        {
            uint32_t sa = (uint32_t)__cvta_generic_to_shared(
                &Abuf[s * SLICE + (row0 + 64) * ROWSTRIDE + kc1]);
            uint32_t sb = (uint32_t)__cvta_generic_to_shared(
                &Bbuf[s * SLICE + (row0 + 64) * ROWSTRIDE + kc1]);
            asm volatile("cp.async.cg.shared.global [%0], [%1], 16;\n"
                         :: "r"(sa), "l"(Ag + (size_t)(row0 + 64) * H_DIM + kof + kc1));
            asm volatile("cp.async.cg.shared.global [%0], [%1], 16;\n"
                         :: "r"(sb), "l"(Wg + (size_t)(row0 + 64) * H_DIM + kof + kc1));
        }
        asm volatile("cp.async.commit_group;\n" ::: "memory");
    }

    int cbuf = 0;           // compute buffer
    int ibuf = STAGES - 1;  // issue buffer (kt + STAGES-1) % STAGES
    if (ibuf >= STAGES) ibuf -= STAGES;

    for (int kt = 0; kt < NK; kt++) {
        asm volatile("cp.async.wait_group 1;\n" ::: "memory");
        __syncthreads();

        // prefetch stage kt + STAGES - 1
        int nxt = kt + STAGES - 1;
        if (nxt < NK) {
            int kof = nxt * BK;
            {
                uint32_t sa = (uint32_t)__cvta_generic_to_shared(
                    &Abuf[ibuf * SLICE + row0 * ROWSTRIDE + kc0]);
                uint32_t sb = (uint32_t)__cvta_generic_to_shared(
                    &Bbuf[ibuf * SLICE + row0 * ROWSTRIDE + kc0]);
                asm volatile("cp.async.cg.shared.global [%0], [%1], 16;\n"
                             :: "r"(sa), "l"(Ag + (size_t)row0 * H_DIM + kof + kc0));
                asm volatile("cp.async.cg.shared.global [%0], [%1], 16;\n"
                             :: "r"(sb), "l"(Wg + (size_t)row0 * H_DIM + kof + kc0));
            }
            {
                uint32_t sa = (uint32_t)__cvta_generic_to_shared(
                    &Abuf[ibuf * SLICE + (row0 + 64) * ROWSTRIDE + kc1]);
                uint32_t sb = (uint32_t)__cvta_generic_to_shared(
                    &Bbuf[ibuf * SLICE + (row0 + 64) * ROWSTRIDE + kc1]);
                asm volatile("cp.async.cg.shared.global [%0], [%1], 16;\n"
                             :: "r"(sa), "l"(Ag + (size_t)(row0 + 64) * H_DIM + kof + kc1));
                asm volatile("cp.async.cg.shared.global [%0], [%1], 16;\n"
                             :: "r"(sb), "l"(Wg + (size_t)(row0 + 64) * H_DIM + kof + kc1));
            }
        }
        asm volatile("cp.async.commit_group;\n" ::: "memory");

        // compute on cbuf (2 k-steps of 8)
        const float* As = Abuf + cbuf * SLICE;
        const float* Bs = Bbuf + cbuf * SLICE;
        #pragma unroll
        for (int ks = 0; ks < 2; ks++) {
            const int k0 = ks * 8;
            uint32_t af[4][4], bf[4][2];
            #pragma unroll
            for (int i = 0; i < 4; i++) {
                const float* base = As + (m0 + i * 16 + gid) * ROWSTRIDE + k0 + tig;
                af[i][0] = f2tf32(base[0]);
                af[i][1] = f2tf32(base[8 * ROWSTRIDE]);
                af[i][2] = f2tf32(base[4]);
                af[i][3] = f2tf32(base[8 * ROWSTRIDE + 4]);
            }
            #pragma unroll
            for (int j = 0; j < 4; j++) {
                const float* base = Bs + (n0 + j * 8 + gid) * ROWSTRIDE + k0 + tig;
                bf[j][0] = f2tf32(base[0]);
                bf[j][1] = f2tf32(base[4]);
            }
            #pragma unroll
            for (int i = 0; i < 4; i++)
                #pragma unroll
                for (int j = 0; j < 4; j++)
                    mma_tf32(acc[i][j], af[i], bf[j]);
        }

        // rotate buffers (no trailing sync needed: issue target is 2 iters old,
        // all warps passed this iter's top barrier before we overwrote it)
        if (++cbuf == STAGES) cbuf = 0;
        if (++ibuf == STAGES) ibuf = 0;
    }

    // epilogue: add bias, write fp32
    const int growbase = brow * BM + m0;
    const int gcolbase = bcol * BN + n0;
    #pragma unroll
    for (int j = 0; j < 4; j++) {
        const int col = gcolbase + j * 8 + 2 * tig;
        const float b0 = bias[col], b1 = bias[col + 1];
        #pragma unroll
        for (int i = 0; i < 4; i++) {
            const int row = growbase + i * 16 + gid;
            float2 v0 = make_float2(acc[i][j][0] + b0, acc[i][j][1] + b1);
            float2 v1 = make_float2(acc[i][j][2] + b0, acc[i][j][3] + b1);
            *(float2*)(C + (size_t)row * O_DIM + col)       = v0;
            *(float2*)(C + (size_t)(row + 8) * O_DIM + col) = v1;
        }
    }
}

// ---------------------------------------------------------------------------
// Kernel 3: LoRA expand (unchanged).
// ---------------------------------------------------------------------------
__global__ __launch_bounds__(256) void lora_expand_kernel(
    const float* __restrict__ lora_b, float* __restrict__ out) {
    int t = blockIdx.y;
    int id = g_idx[t];
    if (id < 0) return;

    __shared__ float s[R_RANK];
    if (threadIdx.x < R_RANK) s[threadIdx.x] = g_shrunk[t * R_RANK + threadIdx.x];
    __syncthreads();

    int o = blockIdx.x * 256 + threadIdx.x;
    const float4* B = (const float4*)(lora_b + (((size_t)id * O_DIM) + o) * R_RANK);
    float4 b0 = B[0], b1 = B[1], b2 = B[2], b3 = B[3];
    float acc = s[0] * b0.x + s[1] * b0.y + s[2] * b0.z + s[3] * b0.w
              + s[4] * b1.x + s[5] * b1.y + s[6] * b1.z + s[7] * b1.w
              + s[8] * b2.x + s[9] * b2.y + s[10] * b2.z + s[11] * b2.w
              + s[12] * b3.x + s[13] * b3.y + s[14] * b3.z + s[15] * b3.w;
    out[(size_t)t * O_DIM + o] += acc;
}

// ---------------------------------------------------------------------------
extern "C" void kernel_launch(void* const* d_in, const int* in_sizes, int n_in,
                              void* d_out, int out_size) {
    const float* x      = (const float*)d_in[0];
    const float* weight = (const float*)d_in[1];
    const float* bias   = (const float*)d_in[2];
    const float* lora_a = (const float*)d_in[3];
    const float* lora_b = (const float*)d_in[4];
    const void*  idxraw = d_in[5];
    float* out = (float*)d_out;

    const int smem_bytes = STAGES * 2 * SLICE * (int)sizeof(float);  // 61440
    cudaFuncSetAttribute(tf32_gemm_bias_kernel,
                         cudaFuncAttributeMaxDynamicSharedMemorySize, smem_bytes);

    prep_indices_kernel<<<1, 1024>>>(idxraw);
    lora_shrink_kernel<<<T_TOK, 256>>>(x, lora_a);
    dim3 ggrid(O_DIM / BN, T_TOK / BM);
    tf32_gemm_bias_kernel<<<ggrid, 256, smem_bytes>>>(x, weight, bias, out);
    dim3 egrid(O_DIM / 256, T_TOK);
    lora_expand_kernel<<<egrid, 256>>>(lora_b, out);
}